// round 7
// baseline (speedup 1.0000x reference)
#include <cuda_runtime.h>
#include <cstdint>
#include <cstddef>

// ---------------------------------------------------------------------------
// Problem constants
// ---------------------------------------------------------------------------
#define B_ROWS 8192
#define MDIM   256
#define NDIM   512
#define NITER  16

// GEMM tiling: CTA 128x128, 8 warps (4 along M x 2 along N), warp tile 32x64
#define MT 128
#define NT 128
#define KC 32               // K per pipeline stage
#define STAGES 3

#define SMEM_PITCH 36       // floats per smem row (bank-conflict-free fragments)
#define STAGE_FLOATS (128 * SMEM_PITCH)            // 4608 floats per tile stage
#define SMEM_B_BASE  (STAGES * STAGE_FLOATS)       // B stages after A stages
#define SMEM_FLOATS  (2 * STAGES * STAGE_FLOATS)   // 27648 floats = 110592 B
#define EPI_PITCH 132       // epilogue staging pitch (floats)

// ---------------------------------------------------------------------------
// Device scratch (static __device__ arrays: allocation-free rule)
// ---------------------------------------------------------------------------
__device__ __align__(1024) float g_G1[NDIM * NDIM];            // D @ S
__device__ __align__(1024) float g_G2[NDIM * NDIM];            // D^T (as [n][k])
__device__ __align__(1024) float g_GW[NDIM * MDIM];            // D @ W
__device__ __align__(1024) float g_WyD[(size_t)B_ROWS * NDIM]; // y @ (D W)^T
__device__ __align__(1024) float g_Sb[(size_t)B_ROWS * NDIM];  // soft_thr(u)

// ---------------------------------------------------------------------------
// PTX helpers (sm_80-level: portable to sm_103 base target)
// ---------------------------------------------------------------------------
__device__ __forceinline__ void cp_async16(uint32_t dst_smem, const void* src) {
    asm volatile("cp.async.cg.shared.global [%0], [%1], 16;"
                 :: "r"(dst_smem), "l"(src) : "memory");
}
__device__ __forceinline__ void cp_commit() {
    asm volatile("cp.async.commit_group;" ::: "memory");
}
template <int N>
__device__ __forceinline__ void cp_wait() {
    asm volatile("cp.async.wait_group %0;" :: "n"(N) : "memory");
}
__device__ __forceinline__ uint32_t f2tf32(float x) {
    uint32_t r;
    asm("cvt.rna.tf32.f32 %0, %1;" : "=r"(r) : "f"(x));
    return r;
}
// split x into hi (tf32) and lo (tf32 of residual): x ~= hi + lo
__device__ __forceinline__ void tf32_split(float x, uint32_t& hi, uint32_t& lo) {
    hi = f2tf32(x);
    lo = f2tf32(x - __uint_as_float(hi));
}
__device__ __forceinline__ void mma_tf32(float* c, const uint32_t* a, const uint32_t* b) {
    asm volatile(
        "mma.sync.aligned.m16n8k8.row.col.f32.tf32.tf32.f32 "
        "{%0,%1,%2,%3},{%4,%5,%6,%7},{%8,%9},{%0,%1,%2,%3};"
        : "+f"(c[0]), "+f"(c[1]), "+f"(c[2]), "+f"(c[3])
        : "r"(a[0]), "r"(a[1]), "r"(a[2]), "r"(a[3]), "r"(b[0]), "r"(b[1]));
}

// ---------------------------------------------------------------------------
// Small precompute kernels
// ---------------------------------------------------------------------------
// C[n][m] = sum_j A[n][j] * X[j][m]   (A: 512 x J row-major, X: J x Mcols)
__global__ void k_small_gemm(const float* __restrict__ A, const float* __restrict__ X,
                             float* __restrict__ C, int Mcols, int J) {
    __shared__ float As[16][17];
    __shared__ float Xs[16][17];
    int tx = threadIdx.x, ty = threadIdx.y;
    int m = blockIdx.x * 16 + tx;
    int n = blockIdx.y * 16 + ty;
    float acc = 0.f;
    for (int j0 = 0; j0 < J; j0 += 16) {
        As[ty][tx] = A[(size_t)n * J + j0 + tx];
        Xs[ty][tx] = X[(size_t)(j0 + ty) * Mcols + m];
        __syncthreads();
#pragma unroll
        for (int jj = 0; jj < 16; jj++) acc += As[ty][jj] * Xs[jj][tx];
        __syncthreads();
    }
    C[(size_t)n * Mcols + m] = acc;
}

// G2[n][k] = D[k][n]
__global__ void k_transpose(const float* __restrict__ D, float* __restrict__ G2) {
    int k = blockIdx.x * 16 + threadIdx.x;
    int n = blockIdx.y * 16 + threadIdx.y;
    G2[(size_t)n * NDIM + k] = D[(size_t)k * NDIM + n];
}

// s = soft_thr(wyd, thr)  (vectorized float4; 8192*512 elements)
__global__ void k_thr0(const float* __restrict__ wyd, float* __restrict__ s,
                       const float* __restrict__ thr_p) {
    const float th = thr_p[0];
    size_t i = (size_t)blockIdx.x * blockDim.x + threadIdx.x;
    float4 v = ((const float4*)wyd)[i];
    v.x = fmaxf(v.x - th, 0.f) - fmaxf(-v.x - th, 0.f);
    v.y = fmaxf(v.y - th, 0.f) - fmaxf(-v.y - th, 0.f);
    v.z = fmaxf(v.z - th, 0.f) - fmaxf(-v.z - th, 0.f);
    v.w = fmaxf(v.w - th, 0.f) - fmaxf(-v.w - th, 0.f);
    ((float4*)s)[i] = v;
}

// ---------------------------------------------------------------------------
// Main 3xtf32 mma.sync GEMM:  C_tile(MTxNT) = A(MTxK) @ Bm(NTxK)^T  (fp32-class)
//   mode 0: store C
//   mode 1: store soft_thr(C + wyd, thr)
// ---------------------------------------------------------------------------
__global__ void __launch_bounds__(256, 1) k_gemm(
    const float* __restrict__ A, const float* __restrict__ Bm,
    int K, int mode, float* __restrict__ outp,
    const float* __restrict__ wyd, const float* __restrict__ thr_p)
{
    extern __shared__ float smf[];
    const int tid  = threadIdx.x;
    const int lane = tid & 31;
    const int warp = tid >> 5;
    const int warpM = warp & 3;       // 0..3  -> rows warpM*32
    const int warpN = warp >> 2;      // 0..1  -> cols warpN*64
    const int lr = lane >> 2;         // 0..7
    const int lc = lane & 3;          // 0..3
    const int row0 = blockIdx.x * MT;
    const int col0 = blockIdx.y * NT;
    const int KB = K >> 5;            // k-blocks of 32

    float c[2][8][4];
#pragma unroll
    for (int mt = 0; mt < 2; ++mt)
#pragma unroll
        for (int nt = 0; nt < 8; ++nt)
#pragma unroll
            for (int q = 0; q < 4; ++q) c[mt][nt][q] = 0.f;

    const float* Abase = A + (size_t)row0 * K;
    const float* Bbase = Bm + (size_t)col0 * K;

    // stage fill: 128 rows x 32 cols per tile, 16B chunks, 256 threads x 4 chunks
    auto fill_stage = [&](int s, int kb) {
        const float* Ag = Abase + kb * KC;
        const float* Bg = Bbase + kb * KC;
#pragma unroll
        for (int i = 0; i < 4; ++i) {
            int ch = tid + i * 256;           // 0..1023
            int r  = ch >> 3;                 // row 0..127
            int cc = ch & 7;                  // 16B chunk in row
            uint32_t da = (uint32_t)__cvta_generic_to_shared(
                &smf[s * STAGE_FLOATS + r * SMEM_PITCH + cc * 4]);
            cp_async16(da, Ag + (size_t)r * K + cc * 4);
            uint32_t db = (uint32_t)__cvta_generic_to_shared(
                &smf[SMEM_B_BASE + s * STAGE_FLOATS + r * SMEM_PITCH + cc * 4]);
            cp_async16(db, Bg + (size_t)r * K + cc * 4);
        }
    };

    // prologue: stages 0..STAGES-2
    fill_stage(0, 0); cp_commit();
    fill_stage(1, 1); cp_commit();

    for (int kb = 0; kb < KB; ++kb) {
        cp_wait<STAGES - 2>();
        __syncthreads();

        // prefetch into the stage consumed STAGES-1 blocks ago
        if (kb + STAGES - 1 < KB) fill_stage((kb + STAGES - 1) % STAGES, kb + STAGES - 1);
        cp_commit();

        const int s = kb % STAGES;
        const float* sA = &smf[s * STAGE_FLOATS];
        const float* sB = &smf[SMEM_B_BASE + s * STAGE_FLOATS];

#pragma unroll
        for (int ks = 0; ks < 4; ++ks) {
            uint32_t ah[2][4], al[2][4], bh[8][2], bl[8][2];
            const int kcol = ks * 8 + lc;
#pragma unroll
            for (int mt = 0; mt < 2; ++mt) {
                const int rb = warpM * 32 + mt * 16;
                tf32_split(sA[(rb + lr)     * SMEM_PITCH + kcol],     ah[mt][0], al[mt][0]);
                tf32_split(sA[(rb + lr + 8) * SMEM_PITCH + kcol],     ah[mt][1], al[mt][1]);
                tf32_split(sA[(rb + lr)     * SMEM_PITCH + kcol + 4], ah[mt][2], al[mt][2]);
                tf32_split(sA[(rb + lr + 8) * SMEM_PITCH + kcol + 4], ah[mt][3], al[mt][3]);
            }
#pragma unroll
            for (int nt = 0; nt < 8; ++nt) {
                const int nb = warpN * 64 + nt * 8;
                tf32_split(sB[(nb + lr) * SMEM_PITCH + kcol],     bh[nt][0], bl[nt][0]);
                tf32_split(sB[(nb + lr) * SMEM_PITCH + kcol + 4], bh[nt][1], bl[nt][1]);
            }
            // 3xtf32: c += a_lo*b_hi + a_hi*b_lo + a_hi*b_hi  (lo*lo dropped)
#pragma unroll
            for (int mt = 0; mt < 2; ++mt)
#pragma unroll
                for (int nt = 0; nt < 8; ++nt) {
                    mma_tf32(c[mt][nt], al[mt], bh[nt]);
                    mma_tf32(c[mt][nt], ah[mt], bl[nt]);
                    mma_tf32(c[mt][nt], ah[mt], bh[nt]);
                }
        }
        __syncthreads();
    }

    // drain pending (empty) cp.async groups before reusing smem
    cp_wait<0>();
    __syncthreads();

    // ---- epilogue: frags -> smem (pitch 132) -> coalesced float4 global ----
#pragma unroll
    for (int mt = 0; mt < 2; ++mt) {
#pragma unroll
        for (int nt = 0; nt < 8; ++nt) {
            const int r = warpM * 32 + mt * 16 + lr;
            const int col = warpN * 64 + nt * 8 + 2 * lc;
            *(float2*)&smf[r * EPI_PITCH + col]       = make_float2(c[mt][nt][0], c[mt][nt][1]);
            *(float2*)&smf[(r + 8) * EPI_PITCH + col] = make_float2(c[mt][nt][2], c[mt][nt][3]);
        }
    }
    __syncthreads();

    const float th = thr_p[0];
#pragma unroll 4
    for (int i = tid; i < 128 * 32; i += 256) {       // 32 float4 per row
        const int r  = i >> 5;
        const int c4 = i & 31;
        float4 v = *(float4*)&smf[r * EPI_PITCH + c4 * 4];
        const size_t g = (size_t)(row0 + r) * NDIM + col0 + c4 * 4;
        if (mode == 1) {
            const float4 w = *(const float4*)&wyd[g];
            float u;
            u = v.x + w.x; v.x = fmaxf(u - th, 0.f) - fmaxf(-u - th, 0.f);
            u = v.y + w.y; v.y = fmaxf(u - th, 0.f) - fmaxf(-u - th, 0.f);
            u = v.z + w.z; v.z = fmaxf(u - th, 0.f) - fmaxf(-u - th, 0.f);
            u = v.w + w.w; v.w = fmaxf(u - th, 0.f) - fmaxf(-u - th, 0.f);
        }
        *(float4*)&outp[g] = v;
    }
}

// ---------------------------------------------------------------------------
// Host side
// ---------------------------------------------------------------------------
extern "C" void kernel_launch(void* const* d_in, const int* in_sizes, int n_in,
                              void* d_out, int out_size) {
    const float* y   = (const float*)d_in[0];
    const float* S   = (const float*)d_in[1];
    const float* W   = (const float*)d_in[2];
    const float* D   = (const float*)d_in[3];
    const float* thr = (const float*)d_in[4];
    float* out = (float*)d_out;

    void *pG1, *pG2, *pGW, *pWyD, *pSb;
    cudaGetSymbolAddress(&pG1, g_G1);
    cudaGetSymbolAddress(&pG2, g_G2);
    cudaGetSymbolAddress(&pGW, g_GW);
    cudaGetSymbolAddress(&pWyD, g_WyD);
    cudaGetSymbolAddress(&pSb, g_Sb);
    float* G1 = (float*)pG1; float* G2 = (float*)pG2; float* GW = (float*)pGW;
    float* WyD = (float*)pWyD; float* Sb = (float*)pSb;

    static bool attr_done = false;
    if (!attr_done) {
        cudaFuncSetAttribute(k_gemm, cudaFuncAttributeMaxDynamicSharedMemorySize,
                             SMEM_FLOATS * 4);
        attr_done = true;
    }

    const size_t slab = (size_t)B_ROWS * NDIM;

    // d0 = 0
    cudaMemsetAsync(out, 0, slab * sizeof(float));

    // Precompute G2 = D^T, G1 = D@S, GW = D@W
    k_transpose<<<dim3(32, 32), dim3(16, 16)>>>(D, G2);
    k_small_gemm<<<dim3(32, 32), dim3(16, 16)>>>(D, S, G1, NDIM, NDIM);
    k_small_gemm<<<dim3(16, 32), dim3(16, 16)>>>(D, W, GW, MDIM, NDIM);

    const dim3 grid(B_ROWS / MT, NDIM / NT);   // (64, 4)
    const dim3 blk(256);
    const size_t smem = SMEM_FLOATS * 4;

    // WyD = y @ GW^T   (K = 256)
    k_gemm<<<grid, blk, smem>>>(y, GW, MDIM, 0, WyD, WyD, thr);

    // t = 0: d0 = 0 -> s = soft_thr(WyD)
    k_thr0<<<(B_ROWS * NDIM / 4) / 256, 256>>>(WyD, Sb, thr);
    // d1 = s @ G2^T
    k_gemm<<<grid, blk, smem>>>(Sb, G2, NDIM, 0, out + slab, WyD, thr);

    for (int t = 1; t < NITER; ++t) {
        // s = soft_thr(d_t @ G1^T + WyD)
        k_gemm<<<grid, blk, smem>>>(out + (size_t)t * slab, G1, NDIM, 1, Sb, WyD, thr);
        // d_{t+1} = s @ G2^T
        k_gemm<<<grid, blk, smem>>>(Sb, G2, NDIM, 0, out + (size_t)(t + 1) * slab, WyD, thr);
    }
}